// round 15
// baseline (speedup 1.0000x reference)
#include <cuda_runtime.h>
#include <cstdint>

// AdditiveAttention: out[b,q,v] = softmax_k( sum_h w_v[h]*tanh(q~[b,q,h]+k~[b,k,h]) ) @ V
// B=4, Q=256, K=1024, IN=256, H=128, V=256.

typedef unsigned long long ull;

// Scratch (__device__ globals — no allocation allowed)
__device__ float g_qp[4 * 256 * 128];         // projected queries
__device__ float g_kp[4 * 1024 * 128];        // projected keys
__device__ float g_pacc[32 * 256 * 256];      // partial acc [b*8+kq][q][v]
__device__ float g_psum[32 * 256];            // partial exp-sums [b*8+kq][q]
__device__ unsigned int g_cnt[64];            // per-(b,qt16) counters (self-reset)

__device__ __forceinline__ float tanh_apx(float x) {
    float y;
    asm("tanh.approx.f32 %0, %1;" : "=f"(y) : "f"(x));
    return y;
}

__device__ __forceinline__ void fma2(ull& d, ull a, ull b) {
    asm("fma.rn.f32x2 %0, %1, %2, %0;" : "+l"(d) : "l"(a), "l"(b));
}

__device__ __forceinline__ ull pack2(float x) {
    ull r;
    asm("mov.b64 %0, {%1, %1};" : "=l"(r) : "f"(x));
    return r;
}

__device__ __forceinline__ void ldgsts16(uint32_t saddr, const void* g) {
    asm volatile("cp.async.cg.shared.global [%0], [%1], 16;"
                 :: "r"(saddr), "l"(g));
}
__device__ __forceinline__ void cp_commit() {
    asm volatile("cp.async.commit_group;" ::: "memory");
}
__device__ __forceinline__ void cp_wait0() {
    asm volatile("cp.async.wait_group 0;" ::: "memory");
}

// ---------------------------------------------------------------------------
// K_proj: projections straight from raw W (no transpose kernel, no spin).
// 160 blocks x 256 threads, 32 rows each: [0,128) keys -> g_kp,
// [128,160) queries -> g_qp.
// Per 32-i tile: thread (h = t>>1, half = t&1) loads W[h][i0+half*16 .. +16]
// via 4 LDG.128 into regs, STS-transposes into wt[buf][i][h] (2-way conflict,
// negligible). Double-buffered: next tile's LDG issued before this tile's
// compute (MLP=4 hides latency under ~480-issue compute body).
// X staged transposed as float2 row-pairs xs2[i*18+p] (as measured-good).
// Inner: per i: 1 LDS.64 w + 2 pack + 4 LDS.64 x + 8 fma2 -> 16 FMAs.
// ---------------------------------------------------------------------------
#define SMEM_PROJ (36864 + 32768)   // xs2 [256][18]f2 + wt [2][32*128]f

__global__ __launch_bounds__(256, 3) void k_proj(
    const float* __restrict__ queries, const float* __restrict__ keys,
    const float* __restrict__ Wq, const float* __restrict__ Wk) {
    extern __shared__ float psm[];
    float2* xs2 = (float2*)psm;          // [256][18] float2
    float*  wt  = psm + 9216;            // [2][32*128] floats

    int bid = blockIdx.x;
    int t = threadIdx.x;

    const float* src;
    const float* W;
    float* dst;
    int r0g;
    if (bid < 128) { src = keys;    W = Wk; dst = g_kp; r0g = bid * 32; }
    else           { src = queries; W = Wq; dst = g_qp; r0g = (bid - 128) * 32; }

    int wh = t >> 1;                 // 0..127 (output feature row of W)
    int whalf = t & 1;               // 0/1 -> i-subrange
    const float4* wrow = (const float4*)(W + wh * 256 + whalf * 16);

    // ---- load W tile 0 into regs ----
    float4 wr0 = wrow[0], wr1 = wrow[1], wr2 = wrow[2], wr3 = wrow[3];

    // ---- stage X transposed into row-pair float2 layout ----
    const float4* s4 = (const float4*)(src + r0g * 256);
    float* xsf = (float*)xs2;
    #pragma unroll 4
    for (int n = 0; n < 8; ++n) {
        int idx4 = t + n * 256;                       // 0..2047 float4
        int r = idx4 >> 6, i4 = idx4 & 63;
        float4 v = s4[idx4];
        xsf[(i4 * 4 + 0) * 36 + r] = v.x;
        xsf[(i4 * 4 + 1) * 36 + r] = v.y;
        xsf[(i4 * 4 + 2) * 36 + r] = v.z;
        xsf[(i4 * 4 + 3) * 36 + r] = v.w;
    }

    // ---- STS tile 0 transposed: wt[0][i][h] ----
    {
        float wv[16];
        *(float4*)&wv[0] = wr0; *(float4*)&wv[4] = wr1;
        *(float4*)&wv[8] = wr2; *(float4*)&wv[12] = wr3;
        #pragma unroll
        for (int j = 0; j < 16; ++j)
            wt[(whalf * 16 + j) * 128 + wh] = wv[j];
    }
    __syncthreads();

    int h2 = (t & 63) * 2;
    int rh = t >> 6;                     // 0..3 -> row-pairs rh*4..rh*4+3
    const float2* xp = xs2 + rh * 4;
    ull acc[4][2] = {{0ull,0ull},{0ull,0ull},{0ull,0ull},{0ull,0ull}};

    for (int tau = 0; tau < 8; ++tau) {
        // issue next tile's LDG early (hidden under compute)
        float4 nr0, nr1, nr2, nr3;
        if (tau + 1 < 8) {
            const float4* nsrc = wrow + (tau + 1) * 8;  // +32 floats
            nr0 = nsrc[0]; nr1 = nsrc[1]; nr2 = nsrc[2]; nr3 = nsrc[3];
        }

        const float* wb = wt + (tau & 1) * 4096;
        #pragma unroll 8
        for (int ii = 0; ii < 32; ++ii) {
            float2 w2 = *(const float2*)&wb[ii * 128 + h2];
            ull wa = pack2(w2.x);
            ull wbp = pack2(w2.y);
            const float2* xi = xp + (tau * 32 + ii) * 18;
            ull x0 = *(const ull*)&xi[0];
            ull x1 = *(const ull*)&xi[1];
            ull x2 = *(const ull*)&xi[2];
            ull x3 = *(const ull*)&xi[3];
            fma2(acc[0][0], x0, wa); fma2(acc[0][1], x0, wbp);
            fma2(acc[1][0], x1, wa); fma2(acc[1][1], x1, wbp);
            fma2(acc[2][0], x2, wa); fma2(acc[2][1], x2, wbp);
            fma2(acc[3][0], x3, wa); fma2(acc[3][1], x3, wbp);
        }

        if (tau + 1 < 8) {
            // write next buffer (readers of it finished before last sync)
            float wv[16];
            *(float4*)&wv[0] = nr0; *(float4*)&wv[4] = nr1;
            *(float4*)&wv[8] = nr2; *(float4*)&wv[12] = nr3;
            float* wn = wt + ((tau + 1) & 1) * 4096;
            #pragma unroll
            for (int j = 0; j < 16; ++j)
                wn[(whalf * 16 + j) * 128 + wh] = wv[j];
            __syncthreads();
        }
    }

    // write 8 rows x 2 h per thread as coalesced float2 (over h)
    #pragma unroll
    for (int p = 0; p < 4; ++p) {
        float2 A = *(float2*)&acc[p][0];   // h2   : {row even, row odd}
        float2 Bv = *(float2*)&acc[p][1];  // h2+1 : {row even, row odd}
        int r = r0g + rh * 8 + p * 2;
        float2 o0 = make_float2(A.x, Bv.x);
        float2 o1 = make_float2(A.y, Bv.y);
        *(float2*)&dst[r * 128 + h2] = o0;
        *(float2*)&dst[(r + 1) * 128 + h2] = o1;
    }
}

// ---------------------------------------------------------------------------
// K_attn8: split-K attn, high arithmetic-intensity mapping (unchanged, R13
// measured 46.3us). 512 blocks: b = bid&3, kq = (bid>>2)&7, qt = bid>>5.
// ---------------------------------------------------------------------------
#define SMEM_ATTN (65536 + 8192 + 512 + 16384 + 128)

__global__ __launch_bounds__(256, 2) void k_attn8(
    const float* __restrict__ values, const int* __restrict__ valid_lens,
    const float* __restrict__ w_v, float* __restrict__ out) {
    extern __shared__ float sm[];
    float4* ks4  = (float4*)sm;                      // [2][2048] float4 64KB
    float*  qs   = sm + 16384;                       // [16][128]        8KB
    float*  wvs  = qs + 2048;                        // [128]
    float2* eb2  = (float2*)(wvs + 128);             // [2][16*64] {e,e} 16KB
    float*  wsum = (float*)(eb2 + 2048);             // [8][4]
    __shared__ unsigned int s_old;

    int bid = blockIdx.x;
    int b = bid & 3;
    int kq = (bid >> 2) & 7;
    int qt = bid >> 5;                // 0..15
    int vlen = valid_lens[b];
    int k0 = kq * 128;
    if (k0 >= vlen) return;
    int nch = min(2, (vlen - k0 + 63) >> 6);

    int t = threadIdx.x;
    int q0 = qt * 16;
    int ka = t & 63;                  // A: key within chunk
    int qg = t >> 6;                  // warp-uniform q-group (0..3)
    int vp = (t & 63) * 4;            // C: 4 v-cols, coalesced

    const float4* kp4 = (const float4*)(g_kp + (b * 1024 + k0) * 128);
    const float* Vb = values + (b * 1024 + k0) * 256;
    uint32_t ksaddr = (uint32_t)__cvta_generic_to_shared(ks4);

    // ---- issue chunk 0 copy (64 k x 32 float4) ----
    #pragma unroll
    for (int n = 0; n < 8; ++n) {
        int idx = t + n * 256;
        int kk = idx >> 5, h4 = idx & 31;
        uint32_t d = ksaddr + (uint32_t)((kk * 32 + ((h4 + kk) & 31)) * 16);
        ldgsts16(d, kp4 + kk * 32 + h4);
    }
    cp_commit();

    // ---- load qs (16 rows), wvs while copy flies ----
    for (int i = t; i < 2048; i += 256)
        qs[i] = g_qp[(b * 256 + q0) * 128 + i];
    if (t < 128) wvs[t] = w_v[t];
    cp_wait0();

    ull acc[4][2] = {{0ull,0ull},{0ull,0ull},{0ull,0ull},{0ull,0ull}};
    float lsum[4] = {0.f, 0.f, 0.f, 0.f};
    const float* qbase = qs + qg * 4 * 128;

    for (int c = 0; c < nch; ++c) {
        __syncthreads();   // chunk c + qs visible; eb(c-1) visible

        if (c + 1 < nch) {
            const float4* srcc = kp4 + 2048;
            #pragma unroll
            for (int n = 0; n < 8; ++n) {
                int idx = t + n * 256;
                int kk = idx >> 5, h4 = idx & 31;
                uint32_t d = ksaddr +
                    (uint32_t)((2048 + kk * 32 + ((h4 + kk) & 31)) * 16);
                ldgsts16(d, srcc + kk * 32 + h4);
            }
            cp_commit();
        }

        const float4* ksb = ks4 + (c & 1) * 2048 + ka * 32;
        float s0 = 0.f, s1 = 0.f, s2 = 0.f, s3 = 0.f;   // 4 q chains

        if (c == 0) {
            #pragma unroll 4
            for (int j = 0; j < 32; ++j) {
                float4 kv = ksb[(j + ka) & 31];
                float4 w4 = *(const float4*)&wvs[j * 4];
                float4 qa0 = *(const float4*)&qbase[j * 4];
                float4 qa1 = *(const float4*)&qbase[128 + j * 4];
                float4 qa2 = *(const float4*)&qbase[256 + j * 4];
                float4 qa3 = *(const float4*)&qbase[384 + j * 4];
                s0 = fmaf(w4.x, tanh_apx(qa0.x + kv.x), s0);
                s0 = fmaf(w4.y, tanh_apx(qa0.y + kv.y), s0);
                s0 = fmaf(w4.z, tanh_apx(qa0.z + kv.z), s0);
                s0 = fmaf(w4.w, tanh_apx(qa0.w + kv.w), s0);
                s1 = fmaf(w4.x, tanh_apx(qa1.x + kv.x), s1);
                s1 = fmaf(w4.y, tanh_apx(qa1.y + kv.y), s1);
                s1 = fmaf(w4.z, tanh_apx(qa1.z + kv.z), s1);
                s1 = fmaf(w4.w, tanh_apx(qa1.w + kv.w), s1);
                s2 = fmaf(w4.x, tanh_apx(qa2.x + kv.x), s2);
                s2 = fmaf(w4.y, tanh_apx(qa2.y + kv.y), s2);
                s2 = fmaf(w4.z, tanh_apx(qa2.z + kv.z), s2);
                s2 = fmaf(w4.w, tanh_apx(qa2.w + kv.w), s2);
                s3 = fmaf(w4.x, tanh_apx(qa3.x + kv.x), s3);
                s3 = fmaf(w4.y, tanh_apx(qa3.y + kv.y), s3);
                s3 = fmaf(w4.z, tanh_apx(qa3.z + kv.z), s3);
                s3 = fmaf(w4.w, tanh_apx(qa3.w + kv.w), s3);
            }
        } else {
            const float2* eb = eb2 + ((c & 1) ^ 1) * 1024 + qg * 4 * 64;
            const float* Vp = Vb + (c - 1) * 64 * 256 + vp;
            #pragma unroll 2
            for (int j = 0; j < 32; ++j) {
                float4 kv = ksb[(j + ka) & 31];
                float4 w4 = *(const float4*)&wvs[j * 4];
                float4 qa0 = *(const float4*)&qbase[j * 4];
                float4 qa1 = *(const float4*)&qbase[128 + j * 4];
                float4 qa2 = *(const float4*)&qbase[256 + j * 4];
                float4 qa3 = *(const float4*)&qbase[384 + j * 4];
                s0 = fmaf(w4.x, tanh_apx(qa0.x + kv.x), s0);
                s0 = fmaf(w4.y, tanh_apx(qa0.y + kv.y), s0);
                s0 = fmaf(w4.z, tanh_apx(qa0.z + kv.z), s0);
                s0 = fmaf(w4.w, tanh_apx(qa0.w + kv.w), s0);
                s1 = fmaf(w4.x, tanh_apx(qa1.x + kv.x), s1);
                s1 = fmaf(w4.y, tanh_apx(qa1.y + kv.y), s1);
                s1 = fmaf(w4.z, tanh_apx(qa1.z + kv.z), s1);
                s1 = fmaf(w4.w, tanh_apx(qa1.w + kv.w), s1);
                s2 = fmaf(w4.x, tanh_apx(qa2.x + kv.x), s2);
                s2 = fmaf(w4.y, tanh_apx(qa2.y + kv.y), s2);
                s2 = fmaf(w4.z, tanh_apx(qa2.z + kv.z), s2);
                s2 = fmaf(w4.w, tanh_apx(qa2.w + kv.w), s2);
                s3 = fmaf(w4.x, tanh_apx(qa3.x + kv.x), s3);
                s3 = fmaf(w4.y, tanh_apx(qa3.y + kv.y), s3);
                s3 = fmaf(w4.z, tanh_apx(qa3.z + kv.z), s3);
                s3 = fmaf(w4.w, tanh_apx(qa3.w + kv.w), s3);
                // Phase C of previous chunk: k = 2j, 2j+1
                #pragma unroll
                for (int dk = 0; dk < 2; ++dk) {
                    int kk = 2 * j + dk;
                    float4 v0 = *(const float4*)&Vp[kk * 256];
                    ull v01 = *(ull*)&v0.x, v23 = *(ull*)&v0.z;
                    float2 e0 = eb[kk];
                    float2 e1 = eb[64 + kk];
                    float2 e2 = eb[128 + kk];
                    float2 e3 = eb[192 + kk];
                    fma2(acc[0][0], *(ull*)&e0, v01);
                    fma2(acc[0][1], *(ull*)&e0, v23);
                    fma2(acc[1][0], *(ull*)&e1, v01);
                    fma2(acc[1][1], *(ull*)&e1, v23);
                    fma2(acc[2][0], *(ull*)&e2, v01);
                    fma2(acc[2][1], *(ull*)&e2, v23);
                    fma2(acc[3][0], *(ull*)&e3, v01);
                    fma2(acc[3][1], *(ull*)&e3, v23);
                }
            }
        }

        // exp + store e (duplicated) for 4 q, masked
        int kg = k0 + c * 64 + ka;
        bool valid = (kg < vlen);
        float e0 = valid ? __expf(s0) : 0.f;
        float e1 = valid ? __expf(s1) : 0.f;
        float e2 = valid ? __expf(s2) : 0.f;
        float e3 = valid ? __expf(s3) : 0.f;
        float2* ebw = eb2 + (c & 1) * 1024 + qg * 4 * 64 + ka;
        ebw[0]   = make_float2(e0, e0);
        ebw[64]  = make_float2(e1, e1);
        ebw[128] = make_float2(e2, e2);
        ebw[192] = make_float2(e3, e3);
        lsum[0] += e0; lsum[1] += e1; lsum[2] += e2; lsum[3] += e3;
        if (c + 1 < nch) cp_wait0();
    }

    // ---- epilogue: C(nch-1) ----
    __syncthreads();
    {
        const float2* eb = eb2 + ((nch - 1) & 1) * 1024 + qg * 4 * 64;
        const float* Vp = Vb + (nch - 1) * 64 * 256 + vp;
        #pragma unroll 4
        for (int kk = 0; kk < 64; ++kk) {
            float4 v0 = *(const float4*)&Vp[kk * 256];
            ull v01 = *(ull*)&v0.x, v23 = *(ull*)&v0.z;
            float2 e0 = eb[kk];
            float2 e1 = eb[64 + kk];
            float2 e2 = eb[128 + kk];
            float2 e3 = eb[192 + kk];
            fma2(acc[0][0], *(ull*)&e0, v01);
            fma2(acc[0][1], *(ull*)&e0, v23);
            fma2(acc[1][0], *(ull*)&e1, v01);
            fma2(acc[1][1], *(ull*)&e1, v23);
            fma2(acc[2][0], *(ull*)&e2, v01);
            fma2(acc[2][1], *(ull*)&e2, v23);
            fma2(acc[3][0], *(ull*)&e3, v01);
            fma2(acc[3][1], *(ull*)&e3, v23);
        }
    }

    // per-q exp sums: warp w covers (qg = w>>1, k-half = w&1); 4 chains each
    #pragma unroll
    for (int qi = 0; qi < 4; ++qi) {
        float v = lsum[qi];
        v += __shfl_xor_sync(0xffffffffu, v, 16);
        v += __shfl_xor_sync(0xffffffffu, v, 8);
        v += __shfl_xor_sync(0xffffffffu, v, 4);
        v += __shfl_xor_sync(0xffffffffu, v, 2);
        v += __shfl_xor_sync(0xffffffffu, v, 1);
        lsum[qi] = v;
    }
    int lane = t & 31, w = t >> 5;
    if (lane == 0) {
        wsum[w * 4 + 0] = lsum[0];
        wsum[w * 4 + 1] = lsum[1];
        wsum[w * 4 + 2] = lsum[2];
        wsum[w * 4 + 3] = lsum[3];
    }
    __syncthreads();
    if (t < 16) {
        int g = t >> 2, qi = t & 3;
        g_psum[(b * 8 + kq) * 256 + q0 + g * 4 + qi] =
            wsum[(2 * g) * 4 + qi] + wsum[(2 * g + 1) * 4 + qi];
    }

    // partial acc write: 4 q rows x 4 v per thread
    #pragma unroll
    for (int qi = 0; qi < 4; ++qi) {
        float* pa = &g_pacc[(((b * 8 + kq) * 256) + q0 + qg * 4 + qi) * 256 + vp];
        float4 o;
        o.x = ((float2*)&acc[qi][0])->x; o.y = ((float2*)&acc[qi][0])->y;
        o.z = ((float2*)&acc[qi][1])->x; o.w = ((float2*)&acc[qi][1])->y;
        *(float4*)pa = o;
    }

    // ---- combine-on-last-arrival per (b, qt) ----
    __threadfence();
    __syncthreads();
    if (t == 0) s_old = atomicAdd(&g_cnt[b * 16 + qt], 1u);
    __syncthreads();

    int np = (vlen + 127) >> 7;           // participants 1..8
    if (s_old == (unsigned)(np - 1)) {
        __threadfence();                  // acquire: peers' partials visible
        for (int qi = 0; qi < 16; ++qi) {
            int qq = q0 + qi;
            float a = 0.f, ssum = 0.f;
            for (int p = 0; p < np; ++p) {
                a += g_pacc[((b * 8 + p) * 256 + qq) * 256 + t];
                ssum += g_psum[(b * 8 + p) * 256 + qq];
            }
            out[(b * 256 + qq) * 256 + t] = a / ssum;
        }
        if (t == 0) atomicExch(&g_cnt[b * 16 + qt], 0u);
    }
}

// ---------------------------------------------------------------------------
extern "C" void kernel_launch(void* const* d_in, const int* in_sizes, int n_in,
                              void* d_out, int out_size) {
    const float* queries    = (const float*)d_in[0];  // [4,256,256]
    const float* keys       = (const float*)d_in[1];  // [4,1024,256]
    const float* values     = (const float*)d_in[2];  // [4,1024,256]
    const int*   valid_lens = (const int*)d_in[3];    // [4]
    const float* W_q        = (const float*)d_in[4];  // [128,256]
    const float* W_k        = (const float*)d_in[5];  // [128,256]
    const float* w_v        = (const float*)d_in[6];  // [128]
    float* out = (float*)d_out;                       // [4,256,256]

    cudaFuncSetAttribute(k_proj, cudaFuncAttributeMaxDynamicSharedMemorySize,
                         SMEM_PROJ);
    cudaFuncSetAttribute(k_attn8, cudaFuncAttributeMaxDynamicSharedMemorySize,
                         SMEM_ATTN);

    k_proj<<<160, 256, SMEM_PROJ>>>(queries, keys, W_q, W_k);
    k_attn8<<<512, 256, SMEM_ATTN>>>(values, valid_lens, w_v, out);
}

// round 16
// speedup vs baseline: 1.0368x; 1.0368x over previous
#include <cuda_runtime.h>
#include <cstdint>

// AdditiveAttention: out[b,q,v] = softmax_k( sum_h w_v[h]*tanh(q~[b,q,h]+k~[b,k,h]) ) @ V
// B=4, Q=256, K=1024, IN=256, H=128, V=256.

typedef unsigned long long ull;

// Scratch (__device__ globals — no allocation allowed)
__device__ float g_qp[4 * 256 * 128];         // projected queries
__device__ float g_kp[4 * 1024 * 128];        // projected keys
__device__ float g_pacc[32 * 256 * 256];      // partial acc [b*8+kq][q][v]
__device__ float g_psum[32 * 256];            // partial exp-sums [b*8+kq][q]
__device__ unsigned int g_cnt[64];            // per-(b,qt16) counters (self-reset)

__device__ __forceinline__ float tanh_apx(float x) {
    float y;
    asm("tanh.approx.f32 %0, %1;" : "=f"(y) : "f"(x));
    return y;
}

__device__ __forceinline__ void fma2(ull& d, ull a, ull b) {
    asm("fma.rn.f32x2 %0, %1, %2, %0;" : "+l"(d) : "l"(a), "l"(b));
}

__device__ __forceinline__ ull pack2(float x) {
    ull r;
    asm("mov.b64 %0, {%1, %1};" : "=l"(r) : "f"(x));
    return r;
}

__device__ __forceinline__ void ldgsts16(uint32_t saddr, const void* g) {
    asm volatile("cp.async.cg.shared.global [%0], [%1], 16;"
                 :: "r"(saddr), "l"(g));
}
__device__ __forceinline__ void cp_commit() {
    asm volatile("cp.async.commit_group;" ::: "memory");
}
__device__ __forceinline__ void cp_wait0() {
    asm volatile("cp.async.wait_group 0;" ::: "memory");
}

// ---------------------------------------------------------------------------
// K_proj: projections straight from raw W (unchanged from R15 — passing).
// 160 blocks x 256 threads, 32 rows each.
// ---------------------------------------------------------------------------
#define SMEM_PROJ (36864 + 32768)   // xs2 [256][18]f2 + wt [2][32*128]f

__global__ __launch_bounds__(256, 3) void k_proj(
    const float* __restrict__ queries, const float* __restrict__ keys,
    const float* __restrict__ Wq, const float* __restrict__ Wk) {
    extern __shared__ float psm[];
    float2* xs2 = (float2*)psm;          // [256][18] float2
    float*  wt  = psm + 9216;            // [2][32*128] floats

    int bid = blockIdx.x;
    int t = threadIdx.x;

    const float* src;
    const float* W;
    float* dst;
    int r0g;
    if (bid < 128) { src = keys;    W = Wk; dst = g_kp; r0g = bid * 32; }
    else           { src = queries; W = Wq; dst = g_qp; r0g = (bid - 128) * 32; }

    int wh = t >> 1;
    int whalf = t & 1;
    const float4* wrow = (const float4*)(W + wh * 256 + whalf * 16);

    float4 wr0 = wrow[0], wr1 = wrow[1], wr2 = wrow[2], wr3 = wrow[3];

    const float4* s4 = (const float4*)(src + r0g * 256);
    float* xsf = (float*)xs2;
    #pragma unroll 4
    for (int n = 0; n < 8; ++n) {
        int idx4 = t + n * 256;
        int r = idx4 >> 6, i4 = idx4 & 63;
        float4 v = s4[idx4];
        xsf[(i4 * 4 + 0) * 36 + r] = v.x;
        xsf[(i4 * 4 + 1) * 36 + r] = v.y;
        xsf[(i4 * 4 + 2) * 36 + r] = v.z;
        xsf[(i4 * 4 + 3) * 36 + r] = v.w;
    }

    {
        float wv[16];
        *(float4*)&wv[0] = wr0; *(float4*)&wv[4] = wr1;
        *(float4*)&wv[8] = wr2; *(float4*)&wv[12] = wr3;
        #pragma unroll
        for (int j = 0; j < 16; ++j)
            wt[(whalf * 16 + j) * 128 + wh] = wv[j];
    }
    __syncthreads();

    int h2 = (t & 63) * 2;
    int rh = t >> 6;
    const float2* xp = xs2 + rh * 4;
    ull acc[4][2] = {{0ull,0ull},{0ull,0ull},{0ull,0ull},{0ull,0ull}};

    for (int tau = 0; tau < 8; ++tau) {
        float4 nr0, nr1, nr2, nr3;
        if (tau + 1 < 8) {
            const float4* nsrc = wrow + (tau + 1) * 8;
            nr0 = nsrc[0]; nr1 = nsrc[1]; nr2 = nsrc[2]; nr3 = nsrc[3];
        }

        const float* wb = wt + (tau & 1) * 4096;
        #pragma unroll 8
        for (int ii = 0; ii < 32; ++ii) {
            float2 w2 = *(const float2*)&wb[ii * 128 + h2];
            ull wa = pack2(w2.x);
            ull wbp = pack2(w2.y);
            const float2* xi = xp + (tau * 32 + ii) * 18;
            ull x0 = *(const ull*)&xi[0];
            ull x1 = *(const ull*)&xi[1];
            ull x2 = *(const ull*)&xi[2];
            ull x3 = *(const ull*)&xi[3];
            fma2(acc[0][0], x0, wa); fma2(acc[0][1], x0, wbp);
            fma2(acc[1][0], x1, wa); fma2(acc[1][1], x1, wbp);
            fma2(acc[2][0], x2, wa); fma2(acc[2][1], x2, wbp);
            fma2(acc[3][0], x3, wa); fma2(acc[3][1], x3, wbp);
        }

        if (tau + 1 < 8) {
            float wv[16];
            *(float4*)&wv[0] = nr0; *(float4*)&wv[4] = nr1;
            *(float4*)&wv[8] = nr2; *(float4*)&wv[12] = nr3;
            float* wn = wt + ((tau + 1) & 1) * 4096;
            #pragma unroll
            for (int j = 0; j < 16; ++j)
                wn[(whalf * 16 + j) * 128 + wh] = wv[j];
            __syncthreads();
        }
    }

    #pragma unroll
    for (int p = 0; p < 4; ++p) {
        float2 A = *(float2*)&acc[p][0];
        float2 Bv = *(float2*)&acc[p][1];
        int r = r0g + rh * 8 + p * 2;
        float2 o0 = make_float2(A.x, Bv.x);
        float2 o1 = make_float2(A.y, Bv.y);
        *(float2*)&dst[r * 128 + h2] = o0;
        *(float2*)&dst[(r + 1) * 128 + h2] = o1;
    }
}

// ---------------------------------------------------------------------------
// K_attn9: R13 geometry with 512 threads/block (16 warps) for MUFU coverage.
// 512 blocks: b = bid&3, kq = (bid>>2)&7 (128-k slice), qt = bid>>5 (16-q
// tile). Per block: <=2 chunks of 64 k, ks double-buffered cp.async with
// rotation swizzle. SMEM 88.7KB -> 2 blocks/SM; 32 warps/SM (8/SMSP).
// Phase A: thread (ka = t&63, qg = (t>>6)&7) computes 2 scores (q = qg*2+qi).
// Phase C (fused into next A iter): thread (qg -> 2 q rows, vp=(t&63)*4).
// Partials -> g_pacc/g_psum; combine-on-last-arrival per (b,qt).
// ---------------------------------------------------------------------------
#define SMEM_ATTN (65536 + 8192 + 512 + 16384 + 128)

__global__ __launch_bounds__(512) void k_attn9(
    const float* __restrict__ values, const int* __restrict__ valid_lens,
    const float* __restrict__ w_v, float* __restrict__ out) {
    extern __shared__ float sm[];
    float4* ks4  = (float4*)sm;                      // [2][2048] float4 64KB
    float*  qs   = sm + 16384;                       // [16][128]        8KB
    float*  wvs  = qs + 2048;                        // [128]
    float2* eb2  = (float2*)(wvs + 128);             // [2][16*64] {e,e} 16KB
    float*  wsum = (float*)(eb2 + 2048);             // [16][2]
    __shared__ unsigned int s_old;

    int bid = blockIdx.x;
    int b = bid & 3;
    int kq = (bid >> 2) & 7;
    int qt = bid >> 5;                // 0..15
    int vlen = valid_lens[b];
    int k0 = kq * 128;
    if (k0 >= vlen) return;
    int nch = min(2, (vlen - k0 + 63) >> 6);

    int t = threadIdx.x;
    int q0 = qt * 16;
    int ka = t & 63;                  // A: key within chunk
    int qg = (t >> 6) & 7;            // warp-uniform q-group (0..7), 2 q each
    int vp = (t & 63) * 4;            // C: 4 v-cols, coalesced

    const float4* kp4 = (const float4*)(g_kp + (b * 1024 + k0) * 128);
    const float* Vb = values + (b * 1024 + k0) * 256;
    uint32_t ksaddr = (uint32_t)__cvta_generic_to_shared(ks4);

    // ---- issue chunk 0 copy (64 k x 32 float4 = 2048) ----
    #pragma unroll
    for (int n = 0; n < 4; ++n) {
        int idx = t + n * 512;
        int kk = idx >> 5, h4 = idx & 31;
        uint32_t d = ksaddr + (uint32_t)((kk * 32 + ((h4 + kk) & 31)) * 16);
        ldgsts16(d, kp4 + kk * 32 + h4);
    }
    cp_commit();

    // ---- load qs (16 rows), wvs while copy flies ----
    for (int i = t; i < 2048; i += 512)
        qs[i] = g_qp[(b * 256 + q0) * 128 + i];
    if (t < 128) wvs[t] = w_v[t];
    cp_wait0();

    ull acc[2][2] = {{0ull,0ull},{0ull,0ull}};
    float lsum[2] = {0.f, 0.f};
    const float* qbase = qs + qg * 2 * 128;

    for (int c = 0; c < nch; ++c) {
        __syncthreads();   // chunk c + qs visible; eb(c-1) visible

        if (c + 1 < nch) {
            const float4* srcc = kp4 + 2048;
            #pragma unroll
            for (int n = 0; n < 4; ++n) {
                int idx = t + n * 512;
                int kk = idx >> 5, h4 = idx & 31;
                uint32_t d = ksaddr +
                    (uint32_t)((2048 + kk * 32 + ((h4 + kk) & 31)) * 16);
                ldgsts16(d, srcc + kk * 32 + h4);
            }
            cp_commit();
        }

        const float4* ksb = ks4 + (c & 1) * 2048 + ka * 32;
        float s0 = 0.f, s1 = 0.f;        // 2 q chains

        if (c == 0) {
            #pragma unroll 4
            for (int j = 0; j < 32; ++j) {
                float4 kv = ksb[(j + ka) & 31];
                float4 w4 = *(const float4*)&wvs[j * 4];
                float4 qa0 = *(const float4*)&qbase[j * 4];
                float4 qa1 = *(const float4*)&qbase[128 + j * 4];
                s0 = fmaf(w4.x, tanh_apx(qa0.x + kv.x), s0);
                s0 = fmaf(w4.y, tanh_apx(qa0.y + kv.y), s0);
                s0 = fmaf(w4.z, tanh_apx(qa0.z + kv.z), s0);
                s0 = fmaf(w4.w, tanh_apx(qa0.w + kv.w), s0);
                s1 = fmaf(w4.x, tanh_apx(qa1.x + kv.x), s1);
                s1 = fmaf(w4.y, tanh_apx(qa1.y + kv.y), s1);
                s1 = fmaf(w4.z, tanh_apx(qa1.z + kv.z), s1);
                s1 = fmaf(w4.w, tanh_apx(qa1.w + kv.w), s1);
            }
        } else {
            const float2* eb = eb2 + ((c & 1) ^ 1) * 1024 + qg * 2 * 64;
            const float* Vp = Vb + (c - 1) * 64 * 256 + vp;
            #pragma unroll 2
            for (int j = 0; j < 32; ++j) {
                float4 kv = ksb[(j + ka) & 31];
                float4 w4 = *(const float4*)&wvs[j * 4];
                float4 qa0 = *(const float4*)&qbase[j * 4];
                float4 qa1 = *(const float4*)&qbase[128 + j * 4];
                s0 = fmaf(w4.x, tanh_apx(qa0.x + kv.x), s0);
                s0 = fmaf(w4.y, tanh_apx(qa0.y + kv.y), s0);
                s0 = fmaf(w4.z, tanh_apx(qa0.z + kv.z), s0);
                s0 = fmaf(w4.w, tanh_apx(qa0.w + kv.w), s0);
                s1 = fmaf(w4.x, tanh_apx(qa1.x + kv.x), s1);
                s1 = fmaf(w4.y, tanh_apx(qa1.y + kv.y), s1);
                s1 = fmaf(w4.z, tanh_apx(qa1.z + kv.z), s1);
                s1 = fmaf(w4.w, tanh_apx(qa1.w + kv.w), s1);
                // Phase C of previous chunk: k = 2j, 2j+1
                #pragma unroll
                for (int dk = 0; dk < 2; ++dk) {
                    int kk = 2 * j + dk;
                    float4 v0 = *(const float4*)&Vp[kk * 256];
                    ull v01 = *(ull*)&v0.x, v23 = *(ull*)&v0.z;
                    float2 e0 = eb[kk];
                    float2 e1 = eb[64 + kk];
                    fma2(acc[0][0], *(ull*)&e0, v01);
                    fma2(acc[0][1], *(ull*)&e0, v23);
                    fma2(acc[1][0], *(ull*)&e1, v01);
                    fma2(acc[1][1], *(ull*)&e1, v23);
                }
            }
        }

        // exp + store e (duplicated) for 2 q, masked
        int kg = k0 + c * 64 + ka;
        bool valid = (kg < vlen);
        float e0 = valid ? __expf(s0) : 0.f;
        float e1 = valid ? __expf(s1) : 0.f;
        float2* ebw = eb2 + (c & 1) * 1024 + qg * 2 * 64 + ka;
        ebw[0]  = make_float2(e0, e0);
        ebw[64] = make_float2(e1, e1);
        lsum[0] += e0; lsum[1] += e1;
        if (c + 1 < nch) cp_wait0();
    }

    // ---- epilogue: C(nch-1) ----
    __syncthreads();
    {
        const float2* eb = eb2 + ((nch - 1) & 1) * 1024 + qg * 2 * 64;
        const float* Vp = Vb + (nch - 1) * 64 * 256 + vp;
        #pragma unroll 4
        for (int kk = 0; kk < 64; ++kk) {
            float4 v0 = *(const float4*)&Vp[kk * 256];
            ull v01 = *(ull*)&v0.x, v23 = *(ull*)&v0.z;
            float2 e0 = eb[kk];
            float2 e1 = eb[64 + kk];
            fma2(acc[0][0], *(ull*)&e0, v01);
            fma2(acc[0][1], *(ull*)&e0, v23);
            fma2(acc[1][0], *(ull*)&e1, v01);
            fma2(acc[1][1], *(ull*)&e1, v23);
        }
    }

    // per-q exp sums: warps 2g, 2g+1 cover qg g (ka halves); 2 chains each
    #pragma unroll
    for (int qi = 0; qi < 2; ++qi) {
        float v = lsum[qi];
        v += __shfl_xor_sync(0xffffffffu, v, 16);
        v += __shfl_xor_sync(0xffffffffu, v, 8);
        v += __shfl_xor_sync(0xffffffffu, v, 4);
        v += __shfl_xor_sync(0xffffffffu, v, 2);
        v += __shfl_xor_sync(0xffffffffu, v, 1);
        lsum[qi] = v;
    }
    int lane = t & 31, w = t >> 5;    // 16 warps
    if (lane == 0) {
        wsum[w * 2 + 0] = lsum[0];
        wsum[w * 2 + 1] = lsum[1];
    }
    __syncthreads();
    if (t < 16) {
        int g = t >> 1, qi = t & 1;
        g_psum[(b * 8 + kq) * 256 + q0 + g * 2 + qi] =
            wsum[(2 * g) * 2 + qi] + wsum[(2 * g + 1) * 2 + qi];
    }

    // partial acc write: 2 q rows x 4 v per thread
    #pragma unroll
    for (int qi = 0; qi < 2; ++qi) {
        float* pa = &g_pacc[(((b * 8 + kq) * 256) + q0 + qg * 2 + qi) * 256 + vp];
        float4 o;
        o.x = ((float2*)&acc[qi][0])->x; o.y = ((float2*)&acc[qi][0])->y;
        o.z = ((float2*)&acc[qi][1])->x; o.w = ((float2*)&acc[qi][1])->y;
        *(float4*)pa = o;
    }

    // ---- combine-on-last-arrival per (b, qt) ----
    __threadfence();
    __syncthreads();
    if (t == 0) s_old = atomicAdd(&g_cnt[b * 16 + qt], 1u);
    __syncthreads();

    int np = (vlen + 127) >> 7;           // participants 1..8
    if (s_old == (unsigned)(np - 1)) {
        __threadfence();                  // acquire: peers' partials visible
        int v = t & 255;                  // 512 threads: split 16 q over 2 halves
        int qh = t >> 8;                  // 0/1 -> q rows qh*8 .. qh*8+7
        for (int qi = 0; qi < 8; ++qi) {
            int qq = q0 + qh * 8 + qi;
            float a = 0.f, ssum = 0.f;
            for (int p = 0; p < np; ++p) {
                a += g_pacc[((b * 8 + p) * 256 + qq) * 256 + v];
                ssum += g_psum[(b * 8 + p) * 256 + qq];
            }
            out[(b * 256 + qq) * 256 + v] = a / ssum;
        }
        if (t == 0) atomicExch(&g_cnt[b * 16 + qt], 0u);
    }
}

// ---------------------------------------------------------------------------
extern "C" void kernel_launch(void* const* d_in, const int* in_sizes, int n_in,
                              void* d_out, int out_size) {
    const float* queries    = (const float*)d_in[0];  // [4,256,256]
    const float* keys       = (const float*)d_in[1];  // [4,1024,256]
    const float* values     = (const float*)d_in[2];  // [4,1024,256]
    const int*   valid_lens = (const int*)d_in[3];    // [4]
    const float* W_q        = (const float*)d_in[4];  // [128,256]
    const float* W_k        = (const float*)d_in[5];  // [128,256]
    const float* w_v        = (const float*)d_in[6];  // [128]
    float* out = (float*)d_out;                       // [4,256,256]

    cudaFuncSetAttribute(k_proj, cudaFuncAttributeMaxDynamicSharedMemorySize,
                         SMEM_PROJ);
    cudaFuncSetAttribute(k_attn9, cudaFuncAttributeMaxDynamicSharedMemorySize,
                         SMEM_ATTN);

    k_proj<<<160, 256, SMEM_PROJ>>>(queries, keys, W_q, W_k);
    k_attn9<<<512, 512, SMEM_ATTN>>>(values, valid_lens, w_v, out);
}